// round 17
// baseline (speedup 1.0000x reference)
#include <cuda_runtime.h>
#include <cuda_bf16.h>
#include <math.h>
#include <stdint.h>

#define TGT   24
#define BSZ   16
#define SRC   400
#define VOCAB 32000
#define DIM   256
#define EMB   256
#define ROWS  (TGT*BSZ)     /* 384 */
#define FEAT  768
#define GATES 1024

// ---------------- scratch (device globals: allocation-free) ----------------
__device__ float g_gx  [ROWS*GATES];
__device__ float g_feat[ROWS*FEAT];
__device__ float g_Ae  [ROWS*SRC];
__device__ float g_psw [ROWS];
__device__ float g_rmax[ROWS];
__device__ float g_rscale[ROWS];
__device__ float g_WhhT[DIM*GATES];     // W_hh transposed: [k][row]

__device__ __nv_bfloat16 g_Wemb_hi[(size_t)VOCAB*EMB];
__device__ __nv_bfloat16 g_Wemb_lo[(size_t)VOCAB*EMB];
__device__ __nv_bfloat16 g_WpT_hi [FEAT*EMB];
__device__ __nv_bfloat16 g_WpT_lo [FEAT*EMB];
__device__ __nv_bfloat16 g_Wih_hi [GATES*EMB];
__device__ __nv_bfloat16 g_Wih_lo [GATES*EMB];
__device__ __nv_bfloat16 g_emb_hi [ROWS*EMB];
__device__ __nv_bfloat16 g_emb_lo [ROWS*EMB];
__device__ __nv_bfloat16 g_feat_hi[ROWS*FEAT];
__device__ __nv_bfloat16 g_feat_lo[ROWS*FEAT];
__device__ __nv_bfloat16 g_Wout_hi[(size_t)VOCAB*FEAT];
__device__ __nv_bfloat16 g_Wout_lo[(size_t)VOCAB*FEAT];

__device__ __forceinline__ float sigm(float x){ return 1.f/(1.f+expf(-x)); }

__device__ __forceinline__ uint32_t smem_to_u32(const void* p) {
    uint32_t a;
    asm("{ .reg .u64 t; cvta.to.shared.u64 t, %1; cvt.u32.u64 %0, t; }" : "=r"(a) : "l"(p));
    return a;
}

#define LDSM4(r0,r1,r2,r3,addr) \
    asm volatile("ldmatrix.sync.aligned.m8n8.x4.shared.b16 {%0,%1,%2,%3}, [%4];" \
        : "=r"(r0),"=r"(r1),"=r"(r2),"=r"(r3) : "r"(addr))

#define MMA16816(d, a, b) \
    asm volatile("mma.sync.aligned.m16n8k16.row.col.f32.bf16.bf16.f32 " \
        "{%0,%1,%2,%3}, {%4,%5,%6,%7}, {%8,%9}, {%0,%1,%2,%3};" \
        : "+f"((d)[0]),"+f"((d)[1]),"+f"((d)[2]),"+f"((d)[3]) \
        : "r"((a)[0]),"r"((a)[1]),"r"((a)[2]),"r"((a)[3]), "r"((b)[0]),"r"((b)[1]))

// =====================================================================
// fp32 -> bf16 hi/lo split kernels
// =====================================================================
__global__ void conv_split(const float* __restrict__ in,
                           __nv_bfloat16* __restrict__ hi, __nv_bfloat16* __restrict__ lo, int n){
    int i = blockIdx.x*256 + threadIdx.x;
    if (i < n) {
        float v = in[i];
        __nv_bfloat16 h = __float2bfloat16(v);
        hi[i] = h;
        lo[i] = __float2bfloat16(v - __bfloat162float(h));
    }
}
// W_proj [EMB x FEAT] -> transposed hi/lo [FEAT x EMB]
__global__ void conv_wpT(const float* __restrict__ Wp,
                         __nv_bfloat16* __restrict__ hi, __nv_bfloat16* __restrict__ lo){
    int o = blockIdx.x*256 + threadIdx.x;   // o < FEAT*EMB
    int n = o >> 8, k = o & 255;
    float v = Wp[k*FEAT + n];
    __nv_bfloat16 h = __float2bfloat16(v);
    hi[o] = h;
    lo[o] = __float2bfloat16(v - __bfloat162float(h));
}
// W_hh [1024 x 256] -> [256 x 1024] fp32 transpose (one-time)
__global__ void transpose_whh(const float* __restrict__ W){
    int idx = blockIdx.x*256 + threadIdx.x;    // < GATES*DIM
    int row = idx >> 8, k = idx & 255;
    g_WhhT[k*GATES + row] = W[idx];
}
// embedding gather from split tables
__global__ void gather_emb2(const int* __restrict__ inp,
                            const __nv_bfloat16* __restrict__ Whi, const __nv_bfloat16* __restrict__ Wlo,
                            __nv_bfloat16* __restrict__ ehi, __nv_bfloat16* __restrict__ elo){
    int r = blockIdx.x, k = threadIdx.x;
    int tok = inp[r];
    ehi[r*EMB + k] = Whi[(size_t)tok*EMB + k];
    elo[r*EMB + k] = Wlo[(size_t)tok*EMB + k];
}

// =====================================================================
// HMMA GEMM (VERBATIM from round 16 — passed at rel_err 1.6e-7):
// 2-stage smem double-buffer + 2-chunk-ahead register prefetch.
// =====================================================================
#define SPAD 40                       /* bf16 elems per smem row (80 B)  */
#define ARRE (128*SPAD)               /* bf16 elems per operand array    */
#define STGE (4*ARRE)                 /* bf16 elems per stage            */
#define GSMEM (2*STGE*2)              /* bytes: 2 stages = 81920         */

template<int EPI>
__global__ __launch_bounds__(256)
void hmma_gemm(const __nv_bfloat16* __restrict__ Ahi, const __nv_bfloat16* __restrict__ Alo,
               const __nv_bfloat16* __restrict__ Bhi, const __nv_bfloat16* __restrict__ Blo,
               int K, int Nst,
               float* __restrict__ Cf, __nv_bfloat16* __restrict__ Chi, __nv_bfloat16* __restrict__ Clo,
               const float* __restrict__ bias1, const float* __restrict__ bias2,
               const int* __restrict__ padp)
{
    extern __shared__ __nv_bfloat16 smem[];
    const uint32_t uS = smem_to_u32(smem);
    const int tid = threadIdx.x;
    const int wid = tid >> 5, lane = tid & 31;
    const int wm = wid >> 2;
    const int wn = wid & 3;
    const int m0 = blockIdx.y * 128, n0 = blockIdx.x * 128;

    const int srow = tid >> 1;
    const int sseg = (tid & 1) * 16;
    const __nv_bfloat16* pAh = Ahi + (size_t)(m0 + srow) * K + sseg;
    const __nv_bfloat16* pAl = Alo + (size_t)(m0 + srow) * K + sseg;
    const __nv_bfloat16* pBh = Bhi + (size_t)(n0 + srow) * K + sseg;
    const __nv_bfloat16* pBl = Blo + (size_t)(n0 + srow) * K + sseg;
    const int soff = srow*SPAD + sseg;

    float acc[4][4][4] = {};
    const int lr = lane & 15, lc = lane >> 4;
    const int nkc = K >> 5;

    uint4 rAh0, rAh1, rAl0, rAl1, rBh0, rBh1, rBl0, rBl1;

    rAh0 = ((const uint4*)pAh)[0]; rAh1 = ((const uint4*)pAh)[1];
    rAl0 = ((const uint4*)pAl)[0]; rAl1 = ((const uint4*)pAl)[1];
    rBh0 = ((const uint4*)pBh)[0]; rBh1 = ((const uint4*)pBh)[1];
    rBl0 = ((const uint4*)pBl)[0]; rBl1 = ((const uint4*)pBl)[1];
    {
        __nv_bfloat16* s0 = smem;
        *(uint4*)(s0          + soff) = rAh0;  *(uint4*)(s0          + soff + 8) = rAh1;
        *(uint4*)(s0 +   ARRE + soff) = rAl0;  *(uint4*)(s0 +   ARRE + soff + 8) = rAl1;
        *(uint4*)(s0 + 2*ARRE + soff) = rBh0;  *(uint4*)(s0 + 2*ARRE + soff + 8) = rBh1;
        *(uint4*)(s0 + 3*ARRE + soff) = rBl0;  *(uint4*)(s0 + 3*ARRE + soff + 8) = rBl1;
    }
    if (nkc > 1) {
        rAh0 = ((const uint4*)pAh)[4]; rAh1 = ((const uint4*)pAh)[5];
        rAl0 = ((const uint4*)pAl)[4]; rAl1 = ((const uint4*)pAl)[5];
        rBh0 = ((const uint4*)pBh)[4]; rBh1 = ((const uint4*)pBh)[5];
        rBl0 = ((const uint4*)pBl)[4]; rBl1 = ((const uint4*)pBl)[5];
    }

    for (int kc = 0; kc < nkc; kc++) {
        __syncthreads();
        if (kc + 1 < nkc) {
            __nv_bfloat16* sN = smem + ((kc + 1) & 1) * STGE;
            *(uint4*)(sN          + soff) = rAh0;  *(uint4*)(sN          + soff + 8) = rAh1;
            *(uint4*)(sN +   ARRE + soff) = rAl0;  *(uint4*)(sN +   ARRE + soff + 8) = rAl1;
            *(uint4*)(sN + 2*ARRE + soff) = rBh0;  *(uint4*)(sN + 2*ARRE + soff + 8) = rBh1;
            *(uint4*)(sN + 3*ARRE + soff) = rBl0;  *(uint4*)(sN + 3*ARRE + soff + 8) = rBl1;
            if (kc + 2 < nkc) {
                const int off = (kc + 2) * 4;
                rAh0 = ((const uint4*)pAh)[off];  rAh1 = ((const uint4*)pAh)[off + 1];
                rAl0 = ((const uint4*)pAl)[off];  rAl1 = ((const uint4*)pAl)[off + 1];
                rBh0 = ((const uint4*)pBh)[off];  rBh1 = ((const uint4*)pBh)[off + 1];
                rBl0 = ((const uint4*)pBl)[off];  rBl1 = ((const uint4*)pBl)[off + 1];
            }
        }

        const uint32_t sb  = uS + (kc & 1) * (STGE * 2);
        const uint32_t bAh = sb,            bAl = sb + ARRE*2;
        const uint32_t bBh = sb + 4*ARRE,   bBl = sb + 6*ARRE;
#pragma unroll
        for (int h = 0; h < 2; h++) {
            uint32_t bh[4][2], bl[4][2];
#pragma unroll
            for (int j2 = 0; j2 < 2; j2++) {
                uint32_t off = (((wn*32 + j2*16 + lr) * SPAD) + h*16 + lc*8) * 2;
                uint32_t r0, r1, r2, r3;
                LDSM4(r0, r1, r2, r3, bBh + off);
                bh[j2*2][0]=r0; bh[j2*2][1]=r2; bh[j2*2+1][0]=r1; bh[j2*2+1][1]=r3;
                LDSM4(r0, r1, r2, r3, bBl + off);
                bl[j2*2][0]=r0; bl[j2*2][1]=r2; bl[j2*2+1][0]=r1; bl[j2*2+1][1]=r3;
            }
#pragma unroll
            for (int i = 0; i < 4; i++) {
                uint32_t off = (((wm*64 + i*16 + lr) * SPAD) + h*16 + lc*8) * 2;
                uint32_t ah[4], al[4];
                LDSM4(ah[0], ah[1], ah[2], ah[3], bAh + off);
                LDSM4(al[0], al[1], al[2], al[3], bAl + off);
#pragma unroll
                for (int j = 0; j < 4; j++) {
                    MMA16816(acc[i][j], ah, bh[j]);
                    MMA16816(acc[i][j], ah, bl[j]);
                    MMA16816(acc[i][j], al, bh[j]);
                }
            }
        }
    }

    const int pad = (EPI == 2) ? *padp : -1;
#pragma unroll
    for (int i = 0; i < 4; i++) {
#pragma unroll
        for (int j = 0; j < 4; j++) {
            const int row0 = m0 + wm*64 + i*16 + (lane >> 2);
            const int col  = n0 + wn*32 + j*8 + 2*(lane & 3);
            if (EPI == 0) {
                float b0 = bias1[col]   + bias2[col];
                float b1 = bias1[col+1] + bias2[col+1];
                *(float2*)(Cf + (size_t)row0    *Nst + col) = make_float2(acc[i][j][0]+b0, acc[i][j][1]+b1);
                *(float2*)(Cf + (size_t)(row0+8)*Nst + col) = make_float2(acc[i][j][2]+b0, acc[i][j][3]+b1);
            } else if (EPI == 1) {
#pragma unroll
                for (int rr = 0; rr < 2; rr++) {
                    float v0 = tanhf(acc[i][j][rr*2+0]);
                    float v1 = tanhf(acc[i][j][rr*2+1]);
                    __nv_bfloat16 h0 = __float2bfloat16(v0);
                    __nv_bfloat16 h1 = __float2bfloat16(v1);
                    __nv_bfloat162 hh; hh.x = h0; hh.y = h1;
                    __nv_bfloat162 ll;
                    ll.x = __float2bfloat16(v0 - __bfloat162float(h0));
                    ll.y = __float2bfloat16(v1 - __bfloat162float(h1));
                    *(__nv_bfloat162*)(Chi + (size_t)(row0+rr*8)*Nst + col) = hh;
                    *(__nv_bfloat162*)(Clo + (size_t)(row0+rr*8)*Nst + col) = ll;
                }
            } else {
                float b0 = bias1[col], b1 = bias1[col+1];
                float v0 = acc[i][j][0]+b0, v1 = acc[i][j][1]+b1;
                float v2 = acc[i][j][2]+b0, v3 = acc[i][j][3]+b1;
                if (col   == pad) { v0 = -INFINITY; v2 = -INFINITY; }
                if (col+1 == pad) { v1 = -INFINITY; v3 = -INFINITY; }
                *(float2*)(Cf + (size_t)row0    *Nst + col) = make_float2(v0, v1);
                *(float2*)(Cf + (size_t)(row0+8)*Nst + col) = make_float2(v2, v3);
            }
        }
    }
}

// =====================================================================
// recurrence4 (VERBATIM from round 16 — passed at rel_err 1.6e-7)
// =====================================================================
#define RSM_BYTES (17240*4)

__global__ __launch_bounds__(1024)
void recurrence4(const float* __restrict__ h0,  const float* __restrict__ c0,
                 const float* __restrict__ W_enc, const float* __restrict__ W_dec,
                 const float* __restrict__ h_e,
                 const float* __restrict__ W_u,  const float* __restrict__ b_u)
{
    extern __shared__ float sm[];
    float* h     = sm;
    float* c     = sm + 256;
    float* q     = sm + 512;
    float* qd    = sm + 768;
    float* gates = sm + 1024;
    float* hdh   = sm + 2048;
    float* sc    = sm + 8192;
    float* Eh    = sm + 8592;
    float* edv   = sm + 8992;
    float* red   = sm + 9016;
    float* scratch = sm + 9048;

    const int b = blockIdx.x, tid = threadIdx.x;
    const int warp = tid >> 5, lane = tid & 31;

    if (tid < DIM) { h[tid] = h0[b*DIM + tid]; c[tid] = c0[b*DIM + tid]; }
    __syncthreads();

    for (int t = 0; t < TGT; t++) {
        const int r = t*BSZ + b;

        {
            const int g  = tid & 255;
            const int kq = tid >> 8;
            const float4* W4 = (const float4*)g_WhhT;
            const int kb = kq * 64;
            float a0=0.f, a1=0.f, a2=0.f, a3=0.f;
#pragma unroll 8
            for (int k = 0; k < 64; k++) {
                float hv = h[kb + k];
                float4 w = W4[(kb + k)*256 + g];
                a0 += hv*w.x; a1 += hv*w.y; a2 += hv*w.z; a3 += hv*w.w;
            }
            if (kq) ((float4*)scratch)[(kq-1)*256 + g] = make_float4(a0, a1, a2, a3);
            __syncthreads();
            if (!kq) {
                float4 p1 = ((float4*)scratch)[g];
                float4 p2 = ((float4*)scratch)[256 + g];
                float4 p3 = ((float4*)scratch)[512 + g];
                float4 gx = *(const float4*)&g_gx[(size_t)r*GATES + g*4];
                gates[g*4+0] = gx.x + a0 + p1.x + p2.x + p3.x;
                gates[g*4+1] = gx.y + a1 + p1.y + p2.y + p3.y;
                gates[g*4+2] = gx.z + a2 + p1.z + p2.z + p3.z;
                gates[g*4+3] = gx.w + a3 + p1.w + p2.w + p3.w;
            }
        }
        __syncthreads();

        float hn = 0.f, cev = 0.f, cdv = 0.f;
        if (tid < DIM) {
            float gi = gates[tid], gf = gates[DIM+tid], gg = gates[2*DIM+tid], go = gates[3*DIM+tid];
            float cn = sigm(gf)*c[tid] + sigm(gi)*tanhf(gg);
            hn = sigm(go)*tanhf(cn);
            h[tid] = hn; c[tid] = cn; hdh[t*256 + tid] = hn;
        }
        __syncthreads();

        {
            const int half = tid >> 9;
            const int g   = tid & 63;
            const int kq8 = (tid >> 6) & 7;
            const float* W = half ? W_dec : W_enc;
            const int kb = kq8 * 32;
            float a0=0.f, a1=0.f, a2=0.f, a3=0.f;
#pragma unroll 8
            for (int k = 0; k < 32; k++) {
                int kk = kb + k;
                float hv = h[kk];
                float4 w = *(const float4*)&W[kk*DIM + g*4];
                a0 += hv*w.x; a1 += hv*w.y; a2 += hv*w.z; a3 += hv*w.w;
            }
            ((float4*)scratch)[(half*8 + kq8)*64 + g] = make_float4(a0, a1, a2, a3);
            __syncthreads();
            if (tid < 512) {
                const int o  = tid & 255;
                const int h2 = tid >> 8;
                float s = 0.f;
#pragma unroll
                for (int i = 0; i < 8; i++)
                    s += scratch[(h2*8 + i)*256 + o];
                if (!h2) q[o] = s; else qd[o] = s;
            }
        }
        __syncthreads();

        {
            float q0=q[lane*4], q1=q[lane*4+1], q2=q[lane*4+2], q3=q[lane*4+3];
            float q4=q[128+lane*4], q5=q[128+lane*4+1], q6=q[128+lane*4+2], q7=q[128+lane*4+3];
            float a0=0,a1=0,a2=0,a3=0,a4=0,a5=0,a6=0,a7=0;
            for (int s = warp; s < SRC; s += 32) {
                const float4* hr = (const float4*)(h_e + ((size_t)s*BSZ + b)*DIM);
                float4 v0 = hr[lane], v1 = hr[32 + lane];
                float p = q0*v0.x+q1*v0.y+q2*v0.z+q3*v0.w + q4*v1.x+q5*v1.y+q6*v1.z+q7*v1.w;
#pragma unroll
                for (int o = 16; o; o >>= 1) p += __shfl_down_sync(0xffffffffu, p, o);
                p = __shfl_sync(0xffffffffu, p, 0);
                float ex = expf(p);
                float ep = Eh[s];
                float EE = (t == 0) ? ex : ex/ep;
                if (lane == 0) { Eh[s] = (t == 0) ? ex : ep + ex; sc[s] = EE; }
                a0 += EE*v0.x; a1 += EE*v0.y; a2 += EE*v0.z; a3 += EE*v0.w;
                a4 += EE*v1.x; a5 += EE*v1.y; a6 += EE*v1.z; a7 += EE*v1.w;
            }
            float4* pcw = (float4*)(scratch + warp*256);
            pcw[lane]      = make_float4(a0, a1, a2, a3);
            pcw[32 + lane] = make_float4(a4, a5, a6, a7);
        }
        __syncthreads();

        {
            float part = (tid < SRC) ? sc[tid] : 0.f;
#pragma unroll
            for (int o = 16; o; o >>= 1) part += __shfl_down_sync(0xffffffffu, part, o);
            if (lane == 0) red[warp] = part;
        }
        __syncthreads();
        if (warp == 0) {
            float v = red[lane];
#pragma unroll
            for (int o = 16; o; o >>= 1) v += __shfl_down_sync(0xffffffffu, v, o);
            if (lane == 0) red[0] = 1.f / v;
        }
        __syncthreads();
        const float invS = red[0];
        if (tid < SRC) g_Ae[(size_t)r*SRC + tid] = sc[tid] * invS;

        {
            float d0=qd[lane*4], d1=qd[lane*4+1], d2=qd[lane*4+2], d3=qd[lane*4+3];
            float d4=qd[128+lane*4], d5=qd[128+lane*4+1], d6=qd[128+lane*4+2], d7=qd[128+lane*4+3];
            for (int j = warp; j <= t; j += 32) {
                const float4* hj = (const float4*)&hdh[j*256];
                float4 v0 = hj[lane], v1 = hj[32 + lane];
                float p = d0*v0.x+d1*v0.y+d2*v0.z+d3*v0.w + d4*v1.x+d5*v1.y+d6*v1.z+d7*v1.w;
#pragma unroll
                for (int o = 16; o; o >>= 1) p += __shfl_down_sync(0xffffffffu, p, o);
                if (lane == 0) edv[j] = expf(p);
            }
        }
        __syncthreads();
        if (tid == 0) {
            float S = 0.f;
            for (int j = 0; j <= t; j++) S += edv[j];
            red[1] = 1.f / S;
        }
        __syncthreads();

        if (tid < DIM) {
            float s = 0.f;
#pragma unroll
            for (int w = 0; w < 32; w++) s += scratch[w*256 + tid];
            cev = s * invS;
            if (t > 0) {
                float sd = 0.f;
                for (int j = 0; j <= t; j++) sd += edv[j]*hdh[j*256 + tid];
                cdv = sd * red[1];
            }
            g_feat[(size_t)r*FEAT + tid]         = hn;
            g_feat[(size_t)r*FEAT + DIM + tid]   = cev;
            g_feat[(size_t)r*FEAT + 2*DIM + tid] = cdv;
        }
        __syncthreads();

        {
            float pp = (tid < DIM) ? (hn*W_u[tid] + cev*W_u[DIM+tid] + cdv*W_u[2*DIM+tid]) : 0.f;
#pragma unroll
            for (int o = 16; o; o >>= 1) pp += __shfl_down_sync(0xffffffffu, pp, o);
            if (lane == 0) red[warp] = pp;
        }
        __syncthreads();
        if (warp == 0) {
            float v = red[lane];
#pragma unroll
            for (int o = 16; o; o >>= 1) v += __shfl_down_sync(0xffffffffu, v, o);
            if (lane == 0) g_psw[r] = sigm(v + b_u[0]);
        }
        __syncthreads();
    }
}

// ---------------- softmax stats (block per row) ----------------
__global__ __launch_bounds__(256)
void rowstats(const float* __restrict__ L)
{
    __shared__ float red[32];
    int r = blockIdx.x, tid = threadIdx.x;
    const float* row = L + (size_t)r*VOCAB;
    float m = -INFINITY;
    for (int v = tid; v < VOCAB; v += 256) m = fmaxf(m, row[v]);
    for (int o = 16; o; o >>= 1) m = fmaxf(m, __shfl_xor_sync(0xffffffffu, m, o));
    if ((tid & 31) == 0) red[tid >> 5] = m;
    __syncthreads();
    if (tid < 8) {
        float v = red[tid];
        for (int o = 4; o; o >>= 1) v = fmaxf(v, __shfl_xor_sync(0xffu, v, o));
        if (tid == 0) red[0] = v;
    }
    __syncthreads();
    m = red[0];
    __syncthreads();
    float s = 0.f;
    for (int v = tid; v < VOCAB; v += 256) s += expf(row[v] - m);
    for (int o = 16; o; o >>= 1) s += __shfl_xor_sync(0xffffffffu, s, o);
    if ((tid & 31) == 0) red[tid >> 5] = s;
    __syncthreads();
    if (tid < 8) {
        float v = red[tid];
        for (int o = 4; o; o >>= 1) v += __shfl_xor_sync(0xffu, v, o);
        if (tid == 0) { g_rmax[r] = m; g_rscale[r] = g_psw[r] / v; }
    }
}

// ---------------- scores = softmax(logits)*p_switch (in place) ----------------
__global__ void scalek(float* __restrict__ out)
{
    int r = blockIdx.y;
    int v = blockIdx.x*256 + threadIdx.x;
    size_t idx = (size_t)r*VOCAB + v;
    out[idx] = expf(out[idx] - g_rmax[r]) * g_rscale[r];
}

// ---------------- copy-attention scatter ----------------
__global__ void scatterk(const int* __restrict__ src, float* __restrict__ out)
{
    int idx = blockIdx.x*256 + threadIdx.x;
    if (idx >= ROWS*SRC) return;
    int s  = idx % SRC;
    int rb = idx / SRC;                 // rb = t*BSZ + b
    int b  = rb % BSZ;
    int v  = src[s*BSZ + b];
    atomicAdd(out + (size_t)rb*VOCAB + v, g_Ae[(size_t)rb*SRC + s] * g_psw[rb]);
}

// ---------------- launch: stream fork/join to hide W_out GEMM ----------------
extern "C" void kernel_launch(void* const* d_in, const int* in_sizes, int n_in,
                              void* d_out, int out_size)
{
    const int*   inp    = (const int*)  d_in[0];
    const int*   src    = (const int*)  d_in[1];
    const float* h_e    = (const float*)d_in[2];
    const float* h0     = (const float*)d_in[3];
    const float* c0     = (const float*)d_in[4];
    const float* W_emb  = (const float*)d_in[5];
    const float* W_ih   = (const float*)d_in[6];
    const float* b_ih   = (const float*)d_in[7];
    const float* W_hh   = (const float*)d_in[8];
    const float* b_hh   = (const float*)d_in[9];
    const float* W_enc  = (const float*)d_in[10];
    const float* W_dec  = (const float*)d_in[11];
    const float* W_proj = (const float*)d_in[12];
    const float* W_u    = (const float*)d_in[13];
    const float* b_u    = (const float*)d_in[14];
    const float* b_out  = (const float*)d_in[15];
    const int*   padp   = (const int*)  d_in[16];
    float* out = (float*)d_out;

    float *p_gx, *p_feat;
    __nv_bfloat16 *p_Wemb_hi, *p_Wemb_lo, *p_WpT_hi, *p_WpT_lo, *p_Wih_hi, *p_Wih_lo;
    __nv_bfloat16 *p_emb_hi, *p_emb_lo, *p_feat_hi, *p_feat_lo, *p_Wout_hi, *p_Wout_lo;
    cudaGetSymbolAddress((void**)&p_gx,      g_gx);
    cudaGetSymbolAddress((void**)&p_feat,    g_feat);
    cudaGetSymbolAddress((void**)&p_Wemb_hi, g_Wemb_hi);
    cudaGetSymbolAddress((void**)&p_Wemb_lo, g_Wemb_lo);
    cudaGetSymbolAddress((void**)&p_WpT_hi,  g_WpT_hi);
    cudaGetSymbolAddress((void**)&p_WpT_lo,  g_WpT_lo);
    cudaGetSymbolAddress((void**)&p_Wih_hi,  g_Wih_hi);
    cudaGetSymbolAddress((void**)&p_Wih_lo,  g_Wih_lo);
    cudaGetSymbolAddress((void**)&p_emb_hi,  g_emb_hi);
    cudaGetSymbolAddress((void**)&p_emb_lo,  g_emb_lo);
    cudaGetSymbolAddress((void**)&p_feat_hi, g_feat_hi);
    cudaGetSymbolAddress((void**)&p_feat_lo, g_feat_lo);
    cudaGetSymbolAddress((void**)&p_Wout_hi, g_Wout_hi);
    cudaGetSymbolAddress((void**)&p_Wout_lo, g_Wout_lo);

    cudaFuncSetAttribute(hmma_gemm<0>, cudaFuncAttributeMaxDynamicSharedMemorySize, GSMEM);
    cudaFuncSetAttribute(hmma_gemm<1>, cudaFuncAttributeMaxDynamicSharedMemorySize, GSMEM);
    cudaFuncSetAttribute(hmma_gemm<2>, cudaFuncAttributeMaxDynamicSharedMemorySize, GSMEM);
    cudaFuncSetAttribute(recurrence4,  cudaFuncAttributeMaxDynamicSharedMemorySize, RSM_BYTES);

    // Side stream + events (created per call; kernel_launch runs only twice,
    // and destroying them mid-capture would invalidate the graph, so leak).
    cudaStream_t s1;
    cudaStreamCreateWithFlags(&s1, cudaStreamNonBlocking);
    cudaEvent_t eFork, eWemb, eJoin;
    cudaEventCreateWithFlags(&eFork, cudaEventDisableTiming);
    cudaEventCreateWithFlags(&eWemb, cudaEventDisableTiming);
    cudaEventCreateWithFlags(&eJoin, cudaEventDisableTiming);

    // ---- main stream: W_emb conversion (needed by both branches) ----
    conv_split<<<(VOCAB*EMB + 255)/256, 256>>>(W_emb, p_Wemb_hi, p_Wemb_lo, VOCAB*EMB);
    cudaEventRecord(eWemb, 0);

    // ---- fork side branch: W_proj conversion + W_out GEMM ----
    cudaEventRecord(eFork, 0);
    cudaStreamWaitEvent(s1, eFork, 0);
    conv_wpT<<<(FEAT*EMB + 255)/256, 256, 0, s1>>>(W_proj, p_WpT_hi, p_WpT_lo);
    cudaStreamWaitEvent(s1, eWemb, 0);
    hmma_gemm<1><<<dim3(FEAT/128, VOCAB/128), 256, GSMEM, s1>>>(
        p_Wemb_hi, p_Wemb_lo, p_WpT_hi, p_WpT_lo, EMB, FEAT,
        nullptr, p_Wout_hi, p_Wout_lo, nullptr, nullptr, nullptr);
    cudaEventRecord(eJoin, s1);

    // ---- main stream: gates chain + recurrence (overlaps W_out GEMM) ----
    conv_split<<<(GATES*EMB + 255)/256, 256>>>(W_ih, p_Wih_hi, p_Wih_lo, GATES*EMB);
    transpose_whh<<<GATES, 256>>>(W_hh);
    gather_emb2<<<ROWS, EMB>>>(inp, p_Wemb_hi, p_Wemb_lo, p_emb_hi, p_emb_lo);
    hmma_gemm<0><<<dim3(GATES/128, ROWS/128), 256, GSMEM>>>(
        p_emb_hi, p_emb_lo, p_Wih_hi, p_Wih_lo, EMB, GATES,
        p_gx, nullptr, nullptr, b_ih, b_hh, nullptr);
    recurrence4<<<BSZ, 1024, RSM_BYTES>>>(h0, c0, W_enc, W_dec, h_e, W_u, b_u);
    conv_split<<<(ROWS*FEAT + 255)/256, 256>>>(p_feat, p_feat_hi, p_feat_lo, ROWS*FEAT);

    // ---- join: logits needs W_out ----
    cudaStreamWaitEvent(0, eJoin, 0);
    hmma_gemm<2><<<dim3(VOCAB/128, ROWS/128), 256, GSMEM>>>(
        p_feat_hi, p_feat_lo, p_Wout_hi, p_Wout_lo, FEAT, VOCAB,
        out, nullptr, nullptr, b_out, nullptr, padp);
    // ---- softmax + scaling + copy scatter ----
    rowstats<<<ROWS, 256>>>(out);
    scalek<<<dim3(VOCAB/256, ROWS), 256>>>(out);
    scatterk<<<(ROWS*SRC + 255)/256, 256>>>(src, out);
}